// round 1
// baseline (speedup 1.0000x reference)
#include <cuda_runtime.h>
#include <math.h>

#define Dq 256
#define Mq 512
#define RB 32
#define NT 512
#define NROWS (32*4096)

// Pre-transposed operands (built once per launch by vm_prep; tiny cost).
__device__ float g_memT[Dq*Mq];   // [k][m]  = memory[m][k]
__device__ float g_WgT[2*Dq*Dq];  // [dc][e] = Wg[e][dc]

typedef unsigned long long u64;

__device__ __forceinline__ u64 bcast2(float v){
    u64 r; asm("mov.b64 %0, {%1, %1};" : "=l"(r) : "f"(v)); return r;
}
__device__ __forceinline__ void unpack2(u64 v, float& lo, float& hi){
    asm("mov.b64 {%0, %1}, %2;" : "=f"(lo), "=f"(hi) : "l"(v));
}
// Packed fp32x2 FMA — 2x FLOP per issue slot vs scalar FFMA on sm_103a.
__device__ __forceinline__ void ffma2(u64& d, u64 a, u64 b){
    asm("fma.rn.f32x2 %0, %1, %2, %0;" : "+l"(d) : "l"(a), "l"(b));
}

__global__ void vm_prep(const float* __restrict__ mem, const float* __restrict__ wg){
    int idx = blockIdx.x*blockDim.x + threadIdx.x;
    if (idx < Mq*Dq){
        int m = idx >> 8, k = idx & 255;      // memory: [512][256]
        g_memT[k*Mq + m] = mem[idx];
        int e = idx >> 9, dc = idx & 511;     // Wg: [256][512]
        g_WgT[dc*Dq + e] = wg[idx];
    }
}

__global__ __launch_bounds__(NT, 1)
void vm_fused(const float* __restrict__ x,
              const float* __restrict__ memv,
              const float* __restrict__ bg,
              float* __restrict__ out_enh,
              float* __restrict__ out_w)
{
    extern __shared__ float smem[];
    float* xsT = smem;                  // [Dq][RB]  x transposed   (32 KB)
    float* ss  = smem + Dq*RB;          // [RB][Mq]  logits/weights (64 KB)
    float* ms  = smem + Dq*RB + RB*Mq;  // [RB][Dq]  memory_read    (32 KB)

    const int tid = threadIdx.x;
    const int rowbase = blockIdx.x * RB;

    // ---------------- Phase A: load x block, transposed into SMEM ----------
    {
        int r  = tid & (RB-1);
        int c4 = tid >> 5;              // 0..15
        #pragma unroll
        for (int cc = 0; cc < 4; cc++){
            int c = c4 + cc*16;         // 0..63 float4-chunks
            float4 v = *(const float4*)(x + (size_t)(rowbase + r)*Dq + c*4);
            xsT[(c*4+0)*RB + r] = v.x;
            xsT[(c*4+1)*RB + r] = v.y;
            xsT[(c*4+2)*RB + r] = v.z;
            xsT[(c*4+3)*RB + r] = v.w;
        }
    }
    __syncthreads();

    const int rg = tid >> 6;            // 0..7  (4 rows each)
    const int cg = tid & 63;            // 0..63
    const int r0 = rg * 4;

    // ---------------- Phase B: similarity  s[32x512] = x @ memory^T --------
    {
        const int c0 = cg * 8;          // 8 cols = 4 f32x2 pairs
        u64 acc[4][4];
        #pragma unroll
        for (int i=0;i<4;i++){
            #pragma unroll
            for (int j=0;j<4;j++) acc[i][j] = 0ull;
        }
        #pragma unroll 4
        for (int k=0;k<Dq;k++){
            float4 av = *(const float4*)(xsT + k*RB + r0);           // broadcast LDS
            const u64* bp = (const u64*)(g_memT + k*Mq + c0);        // L2-resident
            u64 b0 = bp[0], b1 = bp[1], b2 = bp[2], b3 = bp[3];
            u64 a;
            a = bcast2(av.x); ffma2(acc[0][0],a,b0); ffma2(acc[0][1],a,b1); ffma2(acc[0][2],a,b2); ffma2(acc[0][3],a,b3);
            a = bcast2(av.y); ffma2(acc[1][0],a,b0); ffma2(acc[1][1],a,b1); ffma2(acc[1][2],a,b2); ffma2(acc[1][3],a,b3);
            a = bcast2(av.z); ffma2(acc[2][0],a,b0); ffma2(acc[2][1],a,b1); ffma2(acc[2][2],a,b2); ffma2(acc[2][3],a,b3);
            a = bcast2(av.w); ffma2(acc[3][0],a,b0); ffma2(acc[3][1],a,b1); ffma2(acc[3][2],a,b2); ffma2(acc[3][3],a,b3);
        }
        #pragma unroll
        for (int i=0;i<4;i++){
            u64* op = (u64*)(ss + (r0+i)*Mq + c0);
            op[0]=acc[i][0]; op[1]=acc[i][1]; op[2]=acc[i][2]; op[3]=acc[i][3];
        }
    }
    __syncthreads();

    // ---------------- Phase C: softmax rows (2 rows per warp) + write out --
    {
        const int wid = tid >> 5, lane = tid & 31;
        #pragma unroll
        for (int rr = 0; rr < 2; rr++){
            const int r = wid*2 + rr;
            float* row = ss + r*Mq;
            float v[16];
            float mx = -3.402823466e38f;
            #pragma unroll
            for (int t=0;t<16;t++){ v[t] = row[lane + 32*t]; mx = fmaxf(mx, v[t]); }
            #pragma unroll
            for (int o=16;o>0;o>>=1) mx = fmaxf(mx, __shfl_xor_sync(0xffffffffu, mx, o));
            float sum = 0.f;
            #pragma unroll
            for (int t=0;t<16;t++){ v[t] = expf(v[t] - mx); sum += v[t]; }
            #pragma unroll
            for (int o=16;o>0;o>>=1) sum += __shfl_xor_sync(0xffffffffu, sum, o);
            float inv = 1.f / sum;
            float* wout = out_w + (size_t)(rowbase + r)*Mq;
            #pragma unroll
            for (int t=0;t<16;t++){
                float w = v[t]*inv;
                row[lane + 32*t]  = w;   // keep for Phase D
                wout[lane + 32*t] = w;   // coalesced 128B per warp
            }
        }
    }
    __syncthreads();

    // ---------------- Phase D: memory_read  mr[32x256] = w @ memory --------
    {
        const int c0 = cg * 4;          // 4 cols = 2 pairs
        u64 acc[4][2];
        #pragma unroll
        for (int i=0;i<4;i++){ acc[i][0]=0ull; acc[i][1]=0ull; }
        #pragma unroll 4
        for (int k=0;k<Mq;k++){
            const u64* bp = (const u64*)(memv + k*Dq + c0);          // memory is [m][d], k-major already
            u64 b0 = bp[0], b1 = bp[1];
            #pragma unroll
            for (int i=0;i<4;i++){
                u64 a = bcast2(ss[(r0+i)*Mq + k]);                   // broadcast LDS
                ffma2(acc[i][0], a, b0); ffma2(acc[i][1], a, b1);
            }
        }
        #pragma unroll
        for (int i=0;i<4;i++){
            u64* op = (u64*)(ms + (r0+i)*Dq + c0);
            op[0]=acc[i][0]; op[1]=acc[i][1];
        }
    }
    __syncthreads();

    // ---------------- Phase E: gate GEMMs + sigmoid + blend + store --------
    {
        const int e0 = cg * 4;          // 4 gate outputs = 2 pairs
        u64 acc[4][2];
        #pragma unroll
        for (int i=0;i<4;i++){ acc[i][0]=0ull; acc[i][1]=0ull; }
        #pragma unroll 2
        for (int k=0;k<Dq;k+=2){
            float4 av0 = *(const float4*)(xsT + k*RB + r0);
            float4 av1 = *(const float4*)(xsT + (k+1)*RB + r0);
            const u64* p10 = (const u64*)(g_WgT + k*Dq + e0);        // W1 row k
            const u64* p11 = (const u64*)(g_WgT + (k+1)*Dq + e0);
            const u64* p20 = (const u64*)(g_WgT + (Dq+k)*Dq + e0);   // W2 row k
            const u64* p21 = (const u64*)(g_WgT + (Dq+k+1)*Dq + e0);
            u64 c00=p10[0], c01=p10[1], c10=p11[0], c11=p11[1];
            u64 d00=p20[0], d01=p20[1], d10=p21[0], d11=p21[1];
            #pragma unroll
            for (int i=0;i<4;i++){
                float2 a2 = *(const float2*)(ms + (r0+i)*Dq + k);    // mr[r][k..k+1]
                float ax0 = (i==0?av0.x : i==1?av0.y : i==2?av0.z : av0.w);
                float ax1 = (i==0?av1.x : i==1?av1.y : i==2?av1.z : av1.w);
                u64 a;
                a = bcast2(ax0);  ffma2(acc[i][0],a,c00); ffma2(acc[i][1],a,c01);
                a = bcast2(ax1);  ffma2(acc[i][0],a,c10); ffma2(acc[i][1],a,c11);
                a = bcast2(a2.x); ffma2(acc[i][0],a,d00); ffma2(acc[i][1],a,d01);
                a = bcast2(a2.y); ffma2(acc[i][0],a,d10); ffma2(acc[i][1],a,d11);
            }
        }
        float4 bgv = *(const float4*)(bg + e0);
        #pragma unroll
        for (int i=0;i<4;i++){
            float p0,p1,p2,p3;
            unpack2(acc[i][0], p0, p1);
            unpack2(acc[i][1], p2, p3);
            p0 += bgv.x; p1 += bgv.y; p2 += bgv.z; p3 += bgv.w;
            float g0 = 1.f/(1.f+expf(-p0));
            float g1 = 1.f/(1.f+expf(-p1));
            float g2 = 1.f/(1.f+expf(-p2));
            float g3 = 1.f/(1.f+expf(-p3));
            int r = r0 + i;
            float4 mrv = *(const float4*)(ms + r*Dq + e0);
            float x0 = xsT[(e0+0)*RB + r];
            float x1 = xsT[(e0+1)*RB + r];
            float x2 = xsT[(e0+2)*RB + r];
            float x3 = xsT[(e0+3)*RB + r];
            float4 o;
            o.x = x0 + g0*mrv.x;
            o.y = x1 + g1*mrv.y;
            o.z = x2 + g2*mrv.z;
            o.w = x3 + g3*mrv.w;
            *(float4*)(out_enh + (size_t)(rowbase + r)*Dq + e0) = o;
        }
    }
}

extern "C" void kernel_launch(void* const* d_in, const int* in_sizes, int n_in,
                              void* d_out, int out_size)
{
    const float* x    = (const float*)d_in[0];
    const float* memv = (const float*)d_in[1];
    const float* wg   = (const float*)d_in[2];
    const float* bg   = (const float*)d_in[3];

    float* out_enh = (float*)d_out;                       // (B,S,D) first
    float* out_w   = out_enh + (size_t)NROWS * Dq;        // then (B,S,M)

    const size_t smem_bytes = (size_t)(Dq*RB + RB*Mq + RB*Dq) * sizeof(float); // 128 KB
    cudaFuncSetAttribute(vm_fused, cudaFuncAttributeMaxDynamicSharedMemorySize, (int)smem_bytes);

    vm_prep<<<(Mq*Dq + 255)/256, 256>>>(memv, wg);
    vm_fused<<<NROWS/RB, NT, smem_bytes>>>(x, memv, bg, out_enh, out_w);
}

// round 2
// speedup vs baseline: 1.0001x; 1.0001x over previous
#include <cuda_runtime.h>
#include <math.h>

#define Dq 256
#define Mq 512
#define RB 32
#define NT 512
#define NROWS (32*4096)

// Pre-transposed operands (built once per launch by vm_prep; tiny cost).
__device__ float g_memT[Dq*Mq];   // [k][m]  = memory[m][k]
__device__ float g_WgT[2*Dq*Dq];  // [dc][e] = Wg[e][dc]

typedef unsigned long long u64;

__device__ __forceinline__ u64 bcast2(float v){
    u64 r; asm("mov.b64 %0, {%1, %1};" : "=l"(r) : "f"(v)); return r;
}
__device__ __forceinline__ void unpack2(u64 v, float& lo, float& hi){
    asm("mov.b64 {%0, %1}, %2;" : "=f"(lo), "=f"(hi) : "l"(v));
}
// Packed fp32x2 FMA — 2x FLOP per issue slot vs scalar FFMA on sm_103a.
__device__ __forceinline__ void ffma2(u64& d, u64 a, u64 b){
    asm("fma.rn.f32x2 %0, %1, %2, %0;" : "+l"(d) : "l"(a), "l"(b));
}

__global__ void vm_prep(const float* __restrict__ mem, const float* __restrict__ wg){
    int idx = blockIdx.x*blockDim.x + threadIdx.x;
    if (idx < Mq*Dq){
        int m = idx >> 8, k = idx & 255;      // memory: [512][256]
        g_memT[k*Mq + m] = mem[idx];
        int e = idx >> 9, dc = idx & 511;     // Wg: [256][512]
        g_WgT[dc*Dq + e] = wg[idx];
    }
}

__global__ __launch_bounds__(NT, 1)
void vm_fused(const float* __restrict__ x,
              const float* __restrict__ memv,
              const float* __restrict__ bg,
              float* __restrict__ out_enh,
              float* __restrict__ out_w)
{
    extern __shared__ float smem[];
    float* xsT = smem;                  // [Dq][RB]  x transposed   (32 KB)
    float* ss  = smem + Dq*RB;          // [RB][Mq]  logits/weights (64 KB)
    float* ms  = smem + Dq*RB + RB*Mq;  // [RB][Dq]  memory_read    (32 KB)

    const int tid = threadIdx.x;
    const int rowbase = blockIdx.x * RB;

    // ---------------- Phase A: load x block, transposed into SMEM ----------
    {
        int r  = tid & (RB-1);
        int c4 = tid >> 5;              // 0..15
        #pragma unroll
        for (int cc = 0; cc < 4; cc++){
            int c = c4 + cc*16;         // 0..63 float4-chunks
            float4 v = *(const float4*)(x + (size_t)(rowbase + r)*Dq + c*4);
            xsT[(c*4+0)*RB + r] = v.x;
            xsT[(c*4+1)*RB + r] = v.y;
            xsT[(c*4+2)*RB + r] = v.z;
            xsT[(c*4+3)*RB + r] = v.w;
        }
    }
    __syncthreads();

    const int rg = tid >> 6;            // 0..7  (4 rows each)
    const int cg = tid & 63;            // 0..63
    const int r0 = rg * 4;

    // ---------------- Phase B: similarity  s[32x512] = x @ memory^T --------
    {
        const int c0 = cg * 8;          // 8 cols = 4 f32x2 pairs
        u64 acc[4][4];
        #pragma unroll
        for (int i=0;i<4;i++){
            #pragma unroll
            for (int j=0;j<4;j++) acc[i][j] = 0ull;
        }
        #pragma unroll 4
        for (int k=0;k<Dq;k++){
            float4 av = *(const float4*)(xsT + k*RB + r0);           // broadcast LDS
            const u64* bp = (const u64*)(g_memT + k*Mq + c0);        // L2-resident
            u64 b0 = bp[0], b1 = bp[1], b2 = bp[2], b3 = bp[3];
            u64 a;
            a = bcast2(av.x); ffma2(acc[0][0],a,b0); ffma2(acc[0][1],a,b1); ffma2(acc[0][2],a,b2); ffma2(acc[0][3],a,b3);
            a = bcast2(av.y); ffma2(acc[1][0],a,b0); ffma2(acc[1][1],a,b1); ffma2(acc[1][2],a,b2); ffma2(acc[1][3],a,b3);
            a = bcast2(av.z); ffma2(acc[2][0],a,b0); ffma2(acc[2][1],a,b1); ffma2(acc[2][2],a,b2); ffma2(acc[2][3],a,b3);
            a = bcast2(av.w); ffma2(acc[3][0],a,b0); ffma2(acc[3][1],a,b1); ffma2(acc[3][2],a,b2); ffma2(acc[3][3],a,b3);
        }
        #pragma unroll
        for (int i=0;i<4;i++){
            u64* op = (u64*)(ss + (r0+i)*Mq + c0);
            op[0]=acc[i][0]; op[1]=acc[i][1]; op[2]=acc[i][2]; op[3]=acc[i][3];
        }
    }
    __syncthreads();

    // ---------------- Phase C: softmax rows (2 rows per warp) + write out --
    {
        const int wid = tid >> 5, lane = tid & 31;
        #pragma unroll
        for (int rr = 0; rr < 2; rr++){
            const int r = wid*2 + rr;
            float* row = ss + r*Mq;
            float v[16];
            float mx = -3.402823466e38f;
            #pragma unroll
            for (int t=0;t<16;t++){ v[t] = row[lane + 32*t]; mx = fmaxf(mx, v[t]); }
            #pragma unroll
            for (int o=16;o>0;o>>=1) mx = fmaxf(mx, __shfl_xor_sync(0xffffffffu, mx, o));
            float sum = 0.f;
            #pragma unroll
            for (int t=0;t<16;t++){ v[t] = expf(v[t] - mx); sum += v[t]; }
            #pragma unroll
            for (int o=16;o>0;o>>=1) sum += __shfl_xor_sync(0xffffffffu, sum, o);
            float inv = 1.f / sum;
            float* wout = out_w + (size_t)(rowbase + r)*Mq;
            #pragma unroll
            for (int t=0;t<16;t++){
                float w = v[t]*inv;
                row[lane + 32*t]  = w;   // keep for Phase D
                wout[lane + 32*t] = w;   // coalesced 128B per warp
            }
        }
    }
    __syncthreads();

    // ---------------- Phase D: memory_read  mr[32x256] = w @ memory --------
    {
        const int c0 = cg * 4;          // 4 cols = 2 pairs
        u64 acc[4][2];
        #pragma unroll
        for (int i=0;i<4;i++){ acc[i][0]=0ull; acc[i][1]=0ull; }
        #pragma unroll 4
        for (int k=0;k<Mq;k++){
            const u64* bp = (const u64*)(memv + k*Dq + c0);          // memory is [m][d], k-major already
            u64 b0 = bp[0], b1 = bp[1];
            #pragma unroll
            for (int i=0;i<4;i++){
                u64 a = bcast2(ss[(r0+i)*Mq + k]);                   // broadcast LDS
                ffma2(acc[i][0], a, b0); ffma2(acc[i][1], a, b1);
            }
        }
        #pragma unroll
        for (int i=0;i<4;i++){
            u64* op = (u64*)(ms + (r0+i)*Dq + c0);
            op[0]=acc[i][0]; op[1]=acc[i][1];
        }
    }
    __syncthreads();

    // ---------------- Phase E: gate GEMMs + sigmoid + blend + store --------
    {
        const int e0 = cg * 4;          // 4 gate outputs = 2 pairs
        u64 acc[4][2];
        #pragma unroll
        for (int i=0;i<4;i++){ acc[i][0]=0ull; acc[i][1]=0ull; }
        #pragma unroll 2
        for (int k=0;k<Dq;k+=2){
            float4 av0 = *(const float4*)(xsT + k*RB + r0);
            float4 av1 = *(const float4*)(xsT + (k+1)*RB + r0);
            const u64* p10 = (const u64*)(g_WgT + k*Dq + e0);        // W1 row k
            const u64* p11 = (const u64*)(g_WgT + (k+1)*Dq + e0);
            const u64* p20 = (const u64*)(g_WgT + (Dq+k)*Dq + e0);   // W2 row k
            const u64* p21 = (const u64*)(g_WgT + (Dq+k+1)*Dq + e0);
            u64 c00=p10[0], c01=p10[1], c10=p11[0], c11=p11[1];
            u64 d00=p20[0], d01=p20[1], d10=p21[0], d11=p21[1];
            #pragma unroll
            for (int i=0;i<4;i++){
                float2 a2 = *(const float2*)(ms + (r0+i)*Dq + k);    // mr[r][k..k+1]
                float ax0 = (i==0?av0.x : i==1?av0.y : i==2?av0.z : av0.w);
                float ax1 = (i==0?av1.x : i==1?av1.y : i==2?av1.z : av1.w);
                u64 a;
                a = bcast2(ax0);  ffma2(acc[i][0],a,c00); ffma2(acc[i][1],a,c01);
                a = bcast2(ax1);  ffma2(acc[i][0],a,c10); ffma2(acc[i][1],a,c11);
                a = bcast2(a2.x); ffma2(acc[i][0],a,d00); ffma2(acc[i][1],a,d01);
                a = bcast2(a2.y); ffma2(acc[i][0],a,d10); ffma2(acc[i][1],a,d11);
            }
        }
        float4 bgv = *(const float4*)(bg + e0);
        #pragma unroll
        for (int i=0;i<4;i++){
            float p0,p1,p2,p3;
            unpack2(acc[i][0], p0, p1);
            unpack2(acc[i][1], p2, p3);
            p0 += bgv.x; p1 += bgv.y; p2 += bgv.z; p3 += bgv.w;
            float g0 = 1.f/(1.f+expf(-p0));
            float g1 = 1.f/(1.f+expf(-p1));
            float g2 = 1.f/(1.f+expf(-p2));
            float g3 = 1.f/(1.f+expf(-p3));
            int r = r0 + i;
            float4 mrv = *(const float4*)(ms + r*Dq + e0);
            float x0 = xsT[(e0+0)*RB + r];
            float x1 = xsT[(e0+1)*RB + r];
            float x2 = xsT[(e0+2)*RB + r];
            float x3 = xsT[(e0+3)*RB + r];
            float4 o;
            o.x = x0 + g0*mrv.x;
            o.y = x1 + g1*mrv.y;
            o.z = x2 + g2*mrv.z;
            o.w = x3 + g3*mrv.w;
            *(float4*)(out_enh + (size_t)(rowbase + r)*Dq + e0) = o;
        }
    }
}

extern "C" void kernel_launch(void* const* d_in, const int* in_sizes, int n_in,
                              void* d_out, int out_size)
{
    const float* x    = (const float*)d_in[0];
    const float* memv = (const float*)d_in[1];
    const float* wg   = (const float*)d_in[2];
    const float* bg   = (const float*)d_in[3];

    float* out_enh = (float*)d_out;                       // (B,S,D) first
    float* out_w   = out_enh + (size_t)NROWS * Dq;        // then (B,S,M)

    const size_t smem_bytes = (size_t)(Dq*RB + RB*Mq + RB*Dq) * sizeof(float); // 128 KB
    cudaFuncSetAttribute(vm_fused, cudaFuncAttributeMaxDynamicSharedMemorySize, (int)smem_bytes);

    vm_prep<<<(Mq*Dq + 255)/256, 256>>>(memv, wg);
    vm_fused<<<NROWS/RB, NT, smem_bytes>>>(x, memv, bg, out_enh, out_w);
}

// round 3
// speedup vs baseline: 1.7514x; 1.7512x over previous
#include <cuda_runtime.h>
#include <math.h>

#define Dq 256
#define Mq 512
#define RB 32
#define NT 512
#define NROWS (32*4096)

// Padded k-major smem strides (floats). 36 keeps float4 alignment AND spreads banks.
#define WS_STRIDE 36
#define MS_STRIDE 36

// SMEM float offsets
#define XS_OFF   0                       // xsT [256][32]   k-major
#define WS_OFF   (XS_OFF + Dq*RB)        // wsT [512][36]   k-major padded
#define MS_OFF   (WS_OFF + Mq*WS_STRIDE) // msT [256][36]   k-major padded
#define R1_OFF   (MS_OFF + Dq*MS_STRIDE) // pmax [16][32]
#define R2_OFF   (R1_OFF + 512)          // psum [16][32]
#define SMEM_FLOATS (R2_OFF + 512)

// Pre-transposed operands (built by vm_prep; L2-resident, 1.5MB total with memv).
__device__ float g_memT[Dq*Mq];   // [k][m]  = memory[m][k]
__device__ float g_WgT[2*Dq*Dq];  // [dc][e] = Wg[e][dc]

typedef unsigned long long u64;

__device__ __forceinline__ u64 bcast2(float v){
    u64 r; asm("mov.b64 %0, {%1, %1};" : "=l"(r) : "f"(v)); return r;
}
__device__ __forceinline__ void unpack2(u64 v, float& lo, float& hi){
    asm("mov.b64 {%0, %1}, %2;" : "=f"(lo), "=f"(hi) : "l"(v));
}
// Packed fp32x2 FMA
__device__ __forceinline__ void ffma2(u64& d, u64 a, u64 b){
    asm("fma.rn.f32x2 %0, %1, %2, %0;" : "+l"(d) : "l"(a), "l"(b));
}

__global__ void vm_prep(const float* __restrict__ mem, const float* __restrict__ wg){
    int idx = blockIdx.x*blockDim.x + threadIdx.x;
    if (idx < Mq*Dq){
        int m = idx >> 8, k = idx & 255;      // memory: [512][256]
        g_memT[k*Mq + m] = mem[idx];
        int e = idx >> 9, dc = idx & 511;     // Wg: [256][512]
        g_WgT[dc*Dq + e] = wg[idx];
    }
}

__global__ __launch_bounds__(NT, 1)
void vm_fused(const float* __restrict__ x,
              const float* __restrict__ memv,
              const float* __restrict__ bg,
              float* __restrict__ out_enh,
              float* __restrict__ out_w)
{
    extern __shared__ float smem[];
    float* xsT = smem + XS_OFF;   // [k][32]
    float* wsT = smem + WS_OFF;   // [k][36]
    float* msT = smem + MS_OFF;   // [k][36]
    float* red1 = smem + R1_OFF;
    float* red2 = smem + R2_OFF;

    const int tid = threadIdx.x;
    const int rowbase = blockIdx.x * RB;
    const int wid = tid >> 5, lane = tid & 31;

    // warp tiling: rb selects 16-row half, cb selects column block
    const int rb = wid >> 3;           // 0..1
    const int cb = wid & 7;            // 0..7
    const int g  = lane >> 3;          // 0..3  row-quad within half
    const int o  = lane & 7;           // 0..7  col-quad
    const int r0 = rb*16 + g*4;        // 4 contiguous rows per lane

    // ---------------- Phase A: x block -> xsT[k][r] (k-major) --------------
    {
        int r  = lane;
        #pragma unroll
        for (int cc = 0; cc < 4; cc++){
            int c4 = wid + cc*16;       // 0..63 float4-chunks of the row
            float4 v = *(const float4*)(x + (size_t)(rowbase + r)*Dq + c4*4);
            xsT[(c4*4+0)*RB + r] = v.x;
            xsT[(c4*4+1)*RB + r] = v.y;
            xsT[(c4*4+2)*RB + r] = v.z;
            xsT[(c4*4+3)*RB + r] = v.w;
        }
    }
    __syncthreads();

    // ---------------- Phase B: logits[32x512] = x @ memory^T ---------------
    // warp: 16 rows x 64 cols. lane: 4 rows x 8 cols (two coalesced 4-col strips).
    {
        const int c0 = cb*64 + o*4;          // strip 1
        const int c1 = c0 + 32;              // strip 2
        u64 acc[4][4];
        #pragma unroll
        for (int i=0;i<4;i++){ acc[i][0]=0; acc[i][1]=0; acc[i][2]=0; acc[i][3]=0; }

        #pragma unroll 4
        for (int k=0;k<Dq;k++){
            float4 av = *(const float4*)(xsT + k*RB + r0);                 // 1 wf LDS
            ulonglong2 B0 = *(const ulonglong2*)(g_memT + k*Mq + c0);      // 128B coalesced
            ulonglong2 B1 = *(const ulonglong2*)(g_memT + k*Mq + c1);      // 128B coalesced
            u64 a;
            a = bcast2(av.x); ffma2(acc[0][0],a,B0.x); ffma2(acc[0][1],a,B0.y); ffma2(acc[0][2],a,B1.x); ffma2(acc[0][3],a,B1.y);
            a = bcast2(av.y); ffma2(acc[1][0],a,B0.x); ffma2(acc[1][1],a,B0.y); ffma2(acc[1][2],a,B1.x); ffma2(acc[1][3],a,B1.y);
            a = bcast2(av.z); ffma2(acc[2][0],a,B0.x); ffma2(acc[2][1],a,B0.y); ffma2(acc[2][2],a,B1.x); ffma2(acc[2][3],a,B1.y);
            a = bcast2(av.w); ffma2(acc[3][0],a,B0.x); ffma2(acc[3][1],a,B0.y); ffma2(acc[3][2],a,B1.x); ffma2(acc[3][3],a,B1.y);
        }
        // transpose 4x8 in regs, store column-major float4s into wsT[k][r]
        float s[4][8];
        #pragma unroll
        for (int i=0;i<4;i++){
            unpack2(acc[i][0], s[i][0], s[i][1]);
            unpack2(acc[i][1], s[i][2], s[i][3]);
            unpack2(acc[i][2], s[i][4], s[i][5]);
            unpack2(acc[i][3], s[i][6], s[i][7]);
        }
        #pragma unroll
        for (int cc=0; cc<8; cc++){
            int col = (cc<4) ? (c0+cc) : (c1+cc-4);
            float4 v; v.x=s[0][cc]; v.y=s[1][cc]; v.z=s[2][cc]; v.w=s[3][cc];
            *(float4*)(wsT + col*WS_STRIDE + r0) = v;
        }
    }
    __syncthreads();

    // ---------------- Phase C: softmax over k (512) per row ---------------
    // warp w owns k-block [w*32, w*32+32); lane = row. All accesses conflict-free.
    {
        const int k0 = wid*32;
        float v[32];
        float mx = -3.402823466e38f;
        #pragma unroll
        for (int j=0;j<32;j++){ v[j] = wsT[(k0+j)*WS_STRIDE + lane]; mx = fmaxf(mx, v[j]); }
        red1[wid*32 + lane] = mx;
        __syncthreads();
        float rm = -3.402823466e38f;
        #pragma unroll
        for (int i=0;i<16;i++) rm = fmaxf(rm, red1[i*32 + lane]);
        float sm = 0.f;
        #pragma unroll
        for (int j=0;j<32;j++){ v[j] = __expf(v[j]-rm); sm += v[j]; }
        red2[wid*32 + lane] = sm;
        __syncthreads();
        float rs = 0.f;
        #pragma unroll
        for (int i=0;i<16;i++) rs += red2[i*32 + lane];
        float inv = 1.f / rs;
        #pragma unroll
        for (int j=0;j<32;j++) wsT[(k0+j)*WS_STRIDE + lane] = v[j]*inv;
        __syncthreads();
        // coalesced out_w writeout (warp = 2 rows, lanes span k)
        #pragma unroll
        for (int rr=0; rr<2; rr++){
            int r = wid*2 + rr;
            float* wout = out_w + (size_t)(rowbase + r)*Mq;
            #pragma unroll
            for (int t=0;t<16;t++)
                wout[lane + 32*t] = wsT[(lane + 32*t)*WS_STRIDE + r];
        }
    }

    // ---------------- Phase D: mr[32x256] = w @ memory ---------------------
    // warp: 16 rows x 32 cols. lane: 4 rows x 4 cols (contiguous).
    {
        const int c0 = cb*32 + o*4;
        u64 acc[4][2];
        #pragma unroll
        for (int i=0;i<4;i++){ acc[i][0]=0; acc[i][1]=0; }
        #pragma unroll 4
        for (int k=0;k<Mq;k++){
            float4 av = *(const float4*)(wsT + k*WS_STRIDE + r0);          // 1 wf LDS
            ulonglong2 Bv = *(const ulonglong2*)(memv + k*Dq + c0);        // 128B coalesced
            u64 a;
            a = bcast2(av.x); ffma2(acc[0][0],a,Bv.x); ffma2(acc[0][1],a,Bv.y);
            a = bcast2(av.y); ffma2(acc[1][0],a,Bv.x); ffma2(acc[1][1],a,Bv.y);
            a = bcast2(av.z); ffma2(acc[2][0],a,Bv.x); ffma2(acc[2][1],a,Bv.y);
            a = bcast2(av.w); ffma2(acc[3][0],a,Bv.x); ffma2(acc[3][1],a,Bv.y);
        }
        float m[4][4];
        #pragma unroll
        for (int i=0;i<4;i++){
            unpack2(acc[i][0], m[i][0], m[i][1]);
            unpack2(acc[i][1], m[i][2], m[i][3]);
        }
        #pragma unroll
        for (int cc=0; cc<4; cc++){
            float4 v; v.x=m[0][cc]; v.y=m[1][cc]; v.z=m[2][cc]; v.w=m[3][cc];
            *(float4*)(msT + (c0+cc)*MS_STRIDE + r0) = v;
        }
    }
    __syncthreads();

    // ---------------- Phase E: gate + blend --------------------------------
    // warp: 16 rows x 32 e-cols. lane: 4 rows x 4 cols.
    {
        const int e0 = cb*32 + o*4;
        u64 acc[4][2];
        #pragma unroll
        for (int i=0;i<4;i++){ acc[i][0]=0; acc[i][1]=0; }
        #pragma unroll 4
        for (int k=0;k<Dq;k++){
            float4 xa = *(const float4*)(xsT + k*RB + r0);
            float4 ma = *(const float4*)(msT + k*MS_STRIDE + r0);
            ulonglong2 B1 = *(const ulonglong2*)(g_WgT + (size_t)k*Dq + e0);
            ulonglong2 B2 = *(const ulonglong2*)(g_WgT + (size_t)(Dq+k)*Dq + e0);
            u64 a;
            a = bcast2(xa.x); ffma2(acc[0][0],a,B1.x); ffma2(acc[0][1],a,B1.y);
            a = bcast2(ma.x); ffma2(acc[0][0],a,B2.x); ffma2(acc[0][1],a,B2.y);
            a = bcast2(xa.y); ffma2(acc[1][0],a,B1.x); ffma2(acc[1][1],a,B1.y);
            a = bcast2(ma.y); ffma2(acc[1][0],a,B2.x); ffma2(acc[1][1],a,B2.y);
            a = bcast2(xa.z); ffma2(acc[2][0],a,B1.x); ffma2(acc[2][1],a,B1.y);
            a = bcast2(ma.z); ffma2(acc[2][0],a,B2.x); ffma2(acc[2][1],a,B2.y);
            a = bcast2(xa.w); ffma2(acc[3][0],a,B1.x); ffma2(acc[3][1],a,B1.y);
            a = bcast2(ma.w); ffma2(acc[3][0],a,B2.x); ffma2(acc[3][1],a,B2.y);
        }
        // epilogue: gather x and mr column-vectors, sigmoid, blend, store
        float4 bgv = *(const float4*)(bg + e0);
        float xv[4][4], mv[4][4];
        #pragma unroll
        for (int j=0;j<4;j++){
            float4 xc = *(const float4*)(xsT + (e0+j)*RB + r0);
            float4 mc = *(const float4*)(msT + (e0+j)*MS_STRIDE + r0);
            xv[j][0]=xc.x; xv[j][1]=xc.y; xv[j][2]=xc.z; xv[j][3]=xc.w;
            mv[j][0]=mc.x; mv[j][1]=mc.y; mv[j][2]=mc.z; mv[j][3]=mc.w;
        }
        #pragma unroll
        for (int i=0;i<4;i++){
            float p0,p1,p2,p3;
            unpack2(acc[i][0], p0, p1);
            unpack2(acc[i][1], p2, p3);
            p0 += bgv.x; p1 += bgv.y; p2 += bgv.z; p3 += bgv.w;
            float g0 = 1.f/(1.f+__expf(-p0));
            float g1 = 1.f/(1.f+__expf(-p1));
            float g2 = 1.f/(1.f+__expf(-p2));
            float g3 = 1.f/(1.f+__expf(-p3));
            float4 ov;
            ov.x = xv[0][i] + g0*mv[0][i];
            ov.y = xv[1][i] + g1*mv[1][i];
            ov.z = xv[2][i] + g2*mv[2][i];
            ov.w = xv[3][i] + g3*mv[3][i];
            *(float4*)(out_enh + (size_t)(rowbase + r0 + i)*Dq + e0) = ov;
        }
    }
}

extern "C" void kernel_launch(void* const* d_in, const int* in_sizes, int n_in,
                              void* d_out, int out_size)
{
    const float* x    = (const float*)d_in[0];
    const float* memv = (const float*)d_in[1];
    const float* wg   = (const float*)d_in[2];
    const float* bg   = (const float*)d_in[3];

    float* out_enh = (float*)d_out;                       // (B,S,D) first
    float* out_w   = out_enh + (size_t)NROWS * Dq;        // then (B,S,M)

    const size_t smem_bytes = (size_t)SMEM_FLOATS * sizeof(float);  // ~144 KB
    cudaFuncSetAttribute(vm_fused, cudaFuncAttributeMaxDynamicSharedMemorySize, (int)smem_bytes);

    vm_prep<<<(Mq*Dq + 255)/256, 256>>>(memv, wg);
    vm_fused<<<NROWS/RB, NT, smem_bytes>>>(x, memv, bg, out_enh, out_w);
}